// round 9
// baseline (speedup 1.0000x reference)
#include <cuda_runtime.h>
#include <cuda_fp16.h>
#include <cuda_bf16.h>
#include <cstdint>

// ---------------------------------------------------------------------------
// PatchTransformer, two kernels:
//   K1: 7x7 median (reflect pad) in f16x2, two pixels per instruction,
//       60x8 tiles, 288 threads (phases A and B each single-round),
//       570 blocks = single wave.
//   K2: streaming apply, 4-slab coarsened: each thread loads its median
//       float4 pair once and applies it to 4 (b,f) slabs.
// ---------------------------------------------------------------------------

#define PATCH 300
#define CH 3
#define BF_TOTAL 224                    // 16*14
#define PLANE (PATCH * PATCH)           // 90000
#define CHW (CH * PLANE)                // 270000
#define CHW4 (CHW / 4)                  // 67500

__device__ float g_p[CHW];

// ---- packed compare-exchange on 2 pixels: a <- min, b <- max --------------
__device__ __forceinline__ void s2(__half2& a, __half2& b) {
    __half2 t = __hmin2(a, b);
    b = __hmax2(a, b);
    a = t;
}

template <int N>
__device__ __forceinline__ void mnmx(__half2* a) {
#pragma unroll
    for (int i = 0; i < N / 2; i++) s2(a[i], a[N - 1 - i]);
#pragma unroll
    for (int i = 1; i < (N + 1) / 2; i++) s2(a[0], a[i]);
#pragma unroll
    for (int i = N - 2; i >= N / 2; i--) s2(a[i], a[N - 1]);
}

// Exact 7-sorter (pruned Batcher-8), 16 compare-exchanges, on packed pairs.
__device__ __forceinline__ void sort7(__half2* a) {
    s2(a[0], a[1]); s2(a[2], a[3]); s2(a[4], a[5]);
    s2(a[0], a[2]); s2(a[1], a[3]); s2(a[4], a[6]);
    s2(a[1], a[2]); s2(a[5], a[6]);
    s2(a[0], a[4]); s2(a[1], a[5]); s2(a[2], a[6]);
    s2(a[2], a[4]); s2(a[3], a[5]);
    s2(a[1], a[2]); s2(a[3], a[4]); s2(a[5], a[6]);
}

__device__ __forceinline__ int reflect_idx(int t) {
    t = (t < 0) ? -t : t;
    t = (t >= PATCH) ? (2 * PATCH - 2 - t) : t;
    return t;
}

// ---------------- K1: median, 60x8 tile, 570 blocks (single wave) ----------
#define TBW 60
#define TBH 8
#define TILE_W (TBW + 6)   // 66
#define TILE_H (TBH + 6)   // 14
#define TPITCH 68
#define NPAIRROW 4                     // pixel rows 0..3 paired with 4..7
#define NCOLP (TILE_W * NPAIRROW)      // 264 packed column-sort tasks
#define NPAIR (TBW * NPAIRROW)         // 240 packed pixel pairs
#define MTHREADS 288                   // >= NCOLP and >= NPAIR: 1 round each

__global__ __launch_bounds__(MTHREADS)
void median7_kernel(const float* __restrict__ src_all) {
    __shared__ float   tile[TILE_H][TPITCH];
    __shared__ __half2 scol[NCOLP][7];

    const int c  = blockIdx.z;
    const int x0 = blockIdx.x * TBW;
    const int y0 = blockIdx.y * TBH;
    const int tid = threadIdx.x;
    const float* s = src_all + c * PLANE;

    // load raw tile (reflect pad), f32
#pragma unroll
    for (int i = tid; i < TILE_W * TILE_H; i += MTHREADS) {
        const int lx = i % TILE_W;
        const int ly = i / TILE_W;
        const int gx = reflect_idx(x0 - 3 + lx);
        const int gy = reflect_idx(y0 - 3 + ly);
        tile[ly][lx] = s[gy * PATCH + gx];
    }
    __syncthreads();

    // phase A (single round): packed column sorts. Task (yw, col):
    // lo = rows yw..yw+6, hi = rows yw+4..yw+10.
    if (tid < NCOLP) {
        const int yw  = tid / TILE_W;          // 0..3
        const int col = tid - yw * TILE_W;
        __half2 a[7];
#pragma unroll
        for (int r = 0; r < 7; r++)
            a[r] = __floats2half2_rn(tile[yw + r][col], tile[yw + 4 + r][col]);
        sort7(a);
#pragma unroll
        for (int k = 0; k < 7; k++) scol[tid][k] = a[k];
    }
    __syncthreads();

    // phase B (single round): one packed pixel-pair per thread
    if (tid >= NPAIR) return;
    const int yy = tid / TBW;                // 0..3
    const int xx = tid - yy * TBW;           // 0..59
    const int base = yy * TILE_W + xx;

    __half2 S[16];
    __half2 r[7];

#define LOAD_SORT_ROW(I)                                           \
    do {                                                           \
        _Pragma("unroll")                                          \
        for (int dx = 0; dx < 7; dx++) r[dx] = scol[base + dx][I]; \
        sort7(r);                                                  \
    } while (0)

    LOAD_SORT_ROW(2);
    S[0] = r[2]; S[1] = r[3]; S[2] = r[4]; S[3] = r[5]; S[4] = r[6];
    LOAD_SORT_ROW(3);
    S[5] = r[1]; S[6] = r[2]; S[7] = r[3]; S[8] = r[4]; S[9] = r[5];
    LOAD_SORT_ROW(4);
    S[10] = r[0]; S[11] = r[1]; S[12] = r[2]; S[13] = r[3]; S[14] = r[4];
    LOAD_SORT_ROW(1);
    S[15] = r[3];
    __half2 f0 = r[4], f1 = r[5], f2 = r[6];

    mnmx<16>(S); S[0] = f0; S[15] = f1;
    LOAD_SORT_ROW(5);
    mnmx<16>(S); S[0] = f2;   S[15] = r[0];
    mnmx<16>(S); S[0] = r[1]; S[15] = r[2];
    __half2 f3 = r[3];
    LOAD_SORT_ROW(0);
    mnmx<16>(S); S[0] = f3;   S[15] = r[4];
    mnmx<16>(S); S[0] = r[5]; S[15] = r[6];
    LOAD_SORT_ROW(6);
    mnmx<16>(S); S[0] = r[0]; S[15] = r[1];
    mnmx<16>(S); S[0] = r[2];          // live: S[0..14], rank 7 per lane

    mnmx<15>(S);
    mnmx<13>(S + 1);
    mnmx<11>(S + 2);
    mnmx<9>(S + 3);
    mnmx<7>(S + 4);
    mnmx<5>(S + 5);
    s2(S[6], S[7]); s2(S[7], S[8]); s2(S[6], S[7]);

    const int oxy = c * PLANE + (y0 + yy) * PATCH + x0 + xx;
    g_p[oxy] = __low2float(S[7]);                       // pixel (xx, yy)
    if (y0 + yy + 4 < PATCH)
        g_p[oxy + 4 * PATCH] = __high2float(S[7]);      // pixel (xx, yy+4)
#undef LOAD_SORT_ROW
}

// ---------------- K2: apply, 4-slab coarsened -------------------------------
// Thread t -> slab group g = t / POSPAIRS (4 slabs), position pair
// pp = t % POSPAIRS (2 contiguous float4 = 8 floats). Median pair loaded
// once, reused across the 4 slabs. Consecutive threads -> consecutive pos:
// fully coalesced per slab.
#define SLAB_GRP 4
#define POSPAIRS (CHW4 / 2)                         // 33750
#define APPLY_THREADS (POSPAIRS * (BF_TOTAL / SLAB_GRP))   // 1,890,000

__global__ __launch_bounds__(256)
void apply_kernel(const float4* __restrict__ noise,
                  const float* __restrict__ contrast,
                  const float* __restrict__ brightness,
                  float4* __restrict__ out) {
    const unsigned t = blockIdx.x * 256u + threadIdx.x;
    if (t >= APPLY_THREADS) return;

    const unsigned g   = t / (unsigned)POSPAIRS;     // 0..55
    const unsigned pp  = t - g * (unsigned)POSPAIRS;
    const unsigned pos = pp * 2u;                    // float4 index in channel-plane

    const float4* gp4 = reinterpret_cast<const float4*>(g_p);
    const float4 p0 = __ldg(gp4 + pos);
    const float4 p1 = __ldg(gp4 + pos + 1);

    unsigned sl = g * SLAB_GRP;
#pragma unroll
    for (int k = 0; k < SLAB_GRP; k++, sl++) {
        const float cc = __ldg(&contrast[sl]);
        const float bb = __ldg(&brightness[sl]);
        const unsigned idx = sl * (unsigned)CHW4 + pos;

        const float4 n0 = __ldcs(noise + idx);
        const float4 n1 = __ldcs(noise + idx + 1);

        float4 r0, r1;
        r0.x = fminf(fmaxf(fmaf(n0.x, 0.1f, fmaf(p0.x, cc, bb)), 1e-6f), 0.99999f);
        r0.y = fminf(fmaxf(fmaf(n0.y, 0.1f, fmaf(p0.y, cc, bb)), 1e-6f), 0.99999f);
        r0.z = fminf(fmaxf(fmaf(n0.z, 0.1f, fmaf(p0.z, cc, bb)), 1e-6f), 0.99999f);
        r0.w = fminf(fmaxf(fmaf(n0.w, 0.1f, fmaf(p0.w, cc, bb)), 1e-6f), 0.99999f);
        r1.x = fminf(fmaxf(fmaf(n1.x, 0.1f, fmaf(p1.x, cc, bb)), 1e-6f), 0.99999f);
        r1.y = fminf(fmaxf(fmaf(n1.y, 0.1f, fmaf(p1.y, cc, bb)), 1e-6f), 0.99999f);
        r1.z = fminf(fmaxf(fmaf(n1.z, 0.1f, fmaf(p1.z, cc, bb)), 1e-6f), 0.99999f);
        r1.w = fminf(fmaxf(fmaf(n1.w, 0.1f, fmaf(p1.w, cc, bb)), 1e-6f), 0.99999f);

        __stcs(out + idx,     r0);
        __stcs(out + idx + 1, r1);
    }
}

// ---------------------------------------------------------------------------
// Inputs (metadata order):
//   0: adv_patch  [3,300,300] f32
//   1: lab_batch  [16,14,5]   f32 (unused)
//   2: contrast   [16,14]     f32
//   3: brightness [16,14]     f32
//   4: noise      [16,14,3,300,300] f32
//   5: img_size   scalar (unused)
// Output: [16,14,3,300,300] f32
// ---------------------------------------------------------------------------
extern "C" void kernel_launch(void* const* d_in, const int* in_sizes, int n_in,
                              void* d_out, int out_size) {
    const float* adv_patch  = (const float*)d_in[0];
    const float* contrast   = (const float*)d_in[2];
    const float* brightness = (const float*)d_in[3];
    const float* noise      = (const float*)d_in[4];
    float* out = (float*)d_out;

    dim3 mgrd(PATCH / TBW, (PATCH + TBH - 1) / TBH, CH);   // 5 x 38 x 3 = 570
    median7_kernel<<<mgrd, MTHREADS>>>(adv_patch);

    const int blocks = (APPLY_THREADS + 255) / 256;        // 7383
    apply_kernel<<<blocks, 256>>>((const float4*)noise, contrast, brightness,
                                  (float4*)out);
}

// round 11
// speedup vs baseline: 1.0506x; 1.0506x over previous
#include <cuda_runtime.h>
#include <cuda_fp16.h>
#include <cuda_bf16.h>
#include <cstdint>

// ---------------------------------------------------------------------------
// PatchTransformer, two kernels + PDL overlap (fixed launch_dependents
// placement: AFTER the g_p stores, so griddepcontrol.wait orders them):
//   K1: 7x7 median (reflect pad) in f16x2 (two pixels/instr), 60x8 tiles,
//       570 blocks = single wave.
//   K2: streaming apply (proven R8 shape); preamble overlaps K1's tail.
// ---------------------------------------------------------------------------

#define PATCH 300
#define CH 3
#define BF_TOTAL 224                    // 16*14
#define PLANE (PATCH * PATCH)           // 90000
#define CHW (CH * PLANE)                // 270000

__device__ float g_p[CHW];

// ---- packed compare-exchange on 2 pixels: a <- min, b <- max --------------
__device__ __forceinline__ void s2(__half2& a, __half2& b) {
    __half2 t = __hmin2(a, b);
    b = __hmax2(a, b);
    a = t;
}

template <int N>
__device__ __forceinline__ void mnmx(__half2* a) {
#pragma unroll
    for (int i = 0; i < N / 2; i++) s2(a[i], a[N - 1 - i]);
#pragma unroll
    for (int i = 1; i < (N + 1) / 2; i++) s2(a[0], a[i]);
#pragma unroll
    for (int i = N - 2; i >= N / 2; i--) s2(a[i], a[N - 1]);
}

// Exact 7-sorter (pruned Batcher-8), 16 compare-exchanges, on packed pairs.
__device__ __forceinline__ void sort7(__half2* a) {
    s2(a[0], a[1]); s2(a[2], a[3]); s2(a[4], a[5]);
    s2(a[0], a[2]); s2(a[1], a[3]); s2(a[4], a[6]);
    s2(a[1], a[2]); s2(a[5], a[6]);
    s2(a[0], a[4]); s2(a[1], a[5]); s2(a[2], a[6]);
    s2(a[2], a[4]); s2(a[3], a[5]);
    s2(a[1], a[2]); s2(a[3], a[4]); s2(a[5], a[6]);
}

__device__ __forceinline__ int reflect_idx(int t) {
    t = (t < 0) ? -t : t;
    t = (t >= PATCH) ? (2 * PATCH - 2 - t) : t;
    return t;
}

// ---------------- K1: median, 60x8 tile, 570 blocks (single wave) ----------
#define TBW 60
#define TBH 8
#define TILE_W (TBW + 6)   // 66
#define TILE_H (TBH + 6)   // 14
#define TPITCH 68
#define NPAIRROW 4                     // pixel rows 0..3 paired with 4..7
#define NCOLP (TILE_W * NPAIRROW)      // 264 packed column-sort tasks
#define NPAIR (TBW * NPAIRROW)         // 240 packed pixel pairs

__global__ __launch_bounds__(256)
void median7_kernel(const float* __restrict__ src_all) {
    __shared__ float   tile[TILE_H][TPITCH];
    __shared__ __half2 scol[NCOLP][7];

    const int c  = blockIdx.z;
    const int x0 = blockIdx.x * TBW;
    const int y0 = blockIdx.y * TBH;
    const int tid = threadIdx.x;
    const float* s = src_all + c * PLANE;

    // load raw tile (reflect pad), f32
#pragma unroll
    for (int i = tid; i < TILE_W * TILE_H; i += 256) {
        const int lx = i % TILE_W;
        const int ly = i / TILE_W;
        const int gx = reflect_idx(x0 - 3 + lx);
        const int gy = reflect_idx(y0 - 3 + ly);
        tile[ly][lx] = s[gy * PATCH + gx];
    }
    __syncthreads();

    // phase A: packed column sorts. Task (yw, col): lo = rows yw..yw+6,
    // hi = rows yw+4..yw+10.
    for (int t = tid; t < NCOLP; t += 256) {
        const int yw  = t / TILE_W;          // 0..3
        const int col = t - yw * TILE_W;
        __half2 a[7];
#pragma unroll
        for (int r = 0; r < 7; r++)
            a[r] = __floats2half2_rn(tile[yw + r][col], tile[yw + 4 + r][col]);
        sort7(a);
#pragma unroll
        for (int k = 0; k < 7; k++) scol[t][k] = a[k];
    }
    __syncthreads();

    // phase B: one packed pixel-pair per thread (240 of 256 active)
    if (tid < NPAIR) {
        const int yy = tid / TBW;                // 0..3
        const int xx = tid - yy * TBW;           // 0..59
        const int base = yy * TILE_W + xx;

        __half2 S[16];
        __half2 r[7];

#define LOAD_SORT_ROW(I)                                           \
        do {                                                       \
            _Pragma("unroll")                                      \
            for (int dx = 0; dx < 7; dx++) r[dx] = scol[base + dx][I]; \
            sort7(r);                                              \
        } while (0)

        LOAD_SORT_ROW(2);
        S[0] = r[2]; S[1] = r[3]; S[2] = r[4]; S[3] = r[5]; S[4] = r[6];
        LOAD_SORT_ROW(3);
        S[5] = r[1]; S[6] = r[2]; S[7] = r[3]; S[8] = r[4]; S[9] = r[5];
        LOAD_SORT_ROW(4);
        S[10] = r[0]; S[11] = r[1]; S[12] = r[2]; S[13] = r[3]; S[14] = r[4];
        LOAD_SORT_ROW(1);
        S[15] = r[3];
        __half2 f0 = r[4], f1 = r[5], f2 = r[6];

        mnmx<16>(S); S[0] = f0; S[15] = f1;
        LOAD_SORT_ROW(5);
        mnmx<16>(S); S[0] = f2;   S[15] = r[0];
        mnmx<16>(S); S[0] = r[1]; S[15] = r[2];
        __half2 f3 = r[3];
        LOAD_SORT_ROW(0);
        mnmx<16>(S); S[0] = f3;   S[15] = r[4];
        mnmx<16>(S); S[0] = r[5]; S[15] = r[6];
        LOAD_SORT_ROW(6);
        mnmx<16>(S); S[0] = r[0]; S[15] = r[1];
        mnmx<16>(S); S[0] = r[2];          // live: S[0..14], rank 7 per lane

        mnmx<15>(S);
        mnmx<13>(S + 1);
        mnmx<11>(S + 2);
        mnmx<9>(S + 3);
        mnmx<7>(S + 4);
        mnmx<5>(S + 5);
        s2(S[6], S[7]); s2(S[7], S[8]); s2(S[6], S[7]);

        const int oxy = c * PLANE + (y0 + yy) * PATCH + x0 + xx;
        g_p[oxy] = __low2float(S[7]);                       // pixel (xx, yy)
        if (y0 + yy + 4 < PATCH)
            g_p[oxy + 4 * PATCH] = __high2float(S[7]);      // pixel (xx, yy+4)
#undef LOAD_SORT_ROW
    }

    // AFTER all of this thread's g_p stores: signal dependents. PTX
    // guarantees visibility (to a waiting dependent) only of memory ops
    // performed BEFORE this instruction — placement here is load-bearing.
    asm volatile("griddepcontrol.launch_dependents;" ::: "memory");
}

// ---------------- K2: apply (R8 shape + PDL wait) ---------------------------
#define TOTAL4 (BF_TOTAL * CHW / 4)     // 15,120,000
#define HALF4  (TOTAL4 / 2)             // 7,560,000

__global__ __launch_bounds__(256)
void apply_kernel(const float4* __restrict__ noise,
                  const float* __restrict__ contrast,
                  const float* __restrict__ brightness,
                  float4* __restrict__ out) {
    const unsigned gtid = blockIdx.x * 256u + threadIdx.x;
    if (gtid >= HALF4) {
        asm volatile("griddepcontrol.wait;" ::: "memory");
        return;
    }

    const unsigned fi   = gtid * 2u;
    const unsigned flat = fi * 4u;
    const unsigned bf   = flat / (unsigned)CHW;
    const unsigned rem4 = (flat - bf * (unsigned)CHW) >> 2;

    // preamble: everything independent of the median — overlaps K1's tail
    const float4 n0 = __ldcs(noise + fi);
    const float4 n1 = __ldcs(noise + fi + 1);
    const float cc = __ldg(&contrast[bf]);
    const float bb = __ldg(&brightness[bf]);

    // wait for the median grid's signalled (pre-launch_dependents) writes
    asm volatile("griddepcontrol.wait;" ::: "memory");

    const float4* gp4 = reinterpret_cast<const float4*>(g_p);
    const float4 p0 = gp4[rem4];
    const float4 p1 = gp4[rem4 + 1];

    float4 r0, r1;
    r0.x = fminf(fmaxf(fmaf(n0.x, 0.1f, fmaf(p0.x, cc, bb)), 1e-6f), 0.99999f);
    r0.y = fminf(fmaxf(fmaf(n0.y, 0.1f, fmaf(p0.y, cc, bb)), 1e-6f), 0.99999f);
    r0.z = fminf(fmaxf(fmaf(n0.z, 0.1f, fmaf(p0.z, cc, bb)), 1e-6f), 0.99999f);
    r0.w = fminf(fmaxf(fmaf(n0.w, 0.1f, fmaf(p0.w, cc, bb)), 1e-6f), 0.99999f);
    r1.x = fminf(fmaxf(fmaf(n1.x, 0.1f, fmaf(p1.x, cc, bb)), 1e-6f), 0.99999f);
    r1.y = fminf(fmaxf(fmaf(n1.y, 0.1f, fmaf(p1.y, cc, bb)), 1e-6f), 0.99999f);
    r1.z = fminf(fmaxf(fmaf(n1.z, 0.1f, fmaf(p1.z, cc, bb)), 1e-6f), 0.99999f);
    r1.w = fminf(fmaxf(fmaf(n1.w, 0.1f, fmaf(p1.w, cc, bb)), 1e-6f), 0.99999f);

    __stcs(out + fi,     r0);
    __stcs(out + fi + 1, r1);
}

// ---------------------------------------------------------------------------
// Inputs (metadata order):
//   0: adv_patch  [3,300,300] f32
//   1: lab_batch  [16,14,5]   f32 (unused)
//   2: contrast   [16,14]     f32
//   3: brightness [16,14]     f32
//   4: noise      [16,14,3,300,300] f32
//   5: img_size   scalar (unused)
// Output: [16,14,3,300,300] f32
// ---------------------------------------------------------------------------
extern "C" void kernel_launch(void* const* d_in, const int* in_sizes, int n_in,
                              void* d_out, int out_size) {
    const float* adv_patch  = (const float*)d_in[0];
    const float* contrast   = (const float*)d_in[2];
    const float* brightness = (const float*)d_in[3];
    const float* noise      = (const float*)d_in[4];
    float* out = (float*)d_out;

    // K1: median (primary)
    dim3 mgrd(PATCH / TBW, (PATCH + TBH - 1) / TBH, CH);   // 5 x 38 x 3 = 570
    median7_kernel<<<mgrd, 256>>>(adv_patch);

    // K2: apply (dependent, programmatic stream serialization)
    cudaLaunchConfig_t cfg = {};
    cfg.gridDim  = dim3((HALF4 + 255) / 256, 1, 1);
    cfg.blockDim = dim3(256, 1, 1);
    cfg.dynamicSmemBytes = 0;
    cfg.stream = 0;
    cudaLaunchAttribute attrs[1];
    attrs[0].id = cudaLaunchAttributeProgrammaticStreamSerialization;
    attrs[0].val.programmaticStreamSerializationAllowed = 1;
    cfg.attrs = attrs;
    cfg.numAttrs = 1;
    cudaLaunchKernelEx(&cfg, apply_kernel,
                       (const float4*)noise, contrast, brightness, (float4*)out);
}